// round 6
// baseline (speedup 1.0000x reference)
#include <cuda_runtime.h>

#define SPATIAL  3136
#define NBW      128
#define SCALE2   0.35355339059327373f   // 2/sqrt(32)

#define ROWB     896                    // 56 16B lines per channel row
#define TEN      (32 * ROWB)            // 28672 B per tensor tile
#define ACHUNK   (2 * TEN)              // 57344 B (K+V, 8-row chunk)
#define BCH      TEN                    // 28672 B (Q chunk)
#define RED_OFF  (3 * ACHUNK)           // 172032
#define PSD_OFF  (RED_OFF + 32768)      // 204800
#define SMEM_TOT (PSD_OFF + 8192)       // 212992

typedef unsigned long long ull;

__device__ __forceinline__ void fma2(ull& d, ull a, ull b) {
    asm("fma.rn.f32x2 %0, %1, %2, %0;" : "+l"(d) : "l"(a), "l"(b));
}
__device__ __forceinline__ ull rep2(float x) {
    ull r; asm("mov.b64 %0, {%1, %1};" : "=l"(r) : "f"(x)); return r;
}
__device__ __forceinline__ float lo32(ull x) { return __uint_as_float((unsigned)x); }
__device__ __forceinline__ float hi32(ull x) { return __uint_as_float((unsigned)(x >> 32)); }
__device__ __forceinline__ void cp16(unsigned dst, const void* src) {
    asm volatile("cp.async.cg.shared.global [%0], [%1], 16;" :: "r"(dst), "l"(src));
}

__global__ __launch_bounds__(256, 1)
void fused(const float* __restrict__ K, const float* __restrict__ V,
           const float* __restrict__ Q, float* __restrict__ O) {
    extern __shared__ __align__(16) char sm[];
    const unsigned sm32 = (unsigned)__cvta_generic_to_shared(sm);

    const int tid  = threadIdx.x;
    const int bw   = blockIdx.x;
    const int win  = bw & 1;
    const int head = (bw >> 1) & 7;
    const int tb   = bw >> 4;
    const int base = (tb * 256 + head * 32) * SPATIAL + win * 28;

    const int wid  = tid >> 5;
    const int lane = tid & 31;
    const int ti   = lane & 3;          // 8 c1 channels
    const int tj   = lane >> 2;         // 4 c2 channels

    // ---------------- Phase A staging: K+V 8-row chunk, swizzled ----------
    auto stageA = [&](int ch, int buf) {
        const unsigned bufb = sm32 + buf * ACHUNK;
        const int gofs = base + ch * 448;
        #pragma unroll
        for (int it = 0; it < 14; it++) {
            int idx = it * 256 + tid;               // 0..3583
            int tensor = (idx >= 1792) ? 1 : 0;
            int rem = idx - tensor * 1792;          // 0..1791
            int c = rem / 56;
            int g = rem - c * 56;                   // line 0..55
            int r = g / 7;
            int w4 = g - r * 7;
            const float* src = (tensor ? V : K) + gofs + c * SPATIAL + r * 56 + w4 * 4;
            int chs = g ^ ((c >> 2) & 7);
            cp16(bufb + tensor * TEN + c * ROWB + chs * 16, src);
        }
        asm volatile("cp.async.commit_group;");
    };

    ull acc[8][4];
    #pragma unroll
    for (int i = 0; i < 8; i++)
        #pragma unroll
        for (int j = 0; j < 4; j++) acc[i][j] = 0ull;

    stageA(0, 0);
    stageA(1, 1);

    for (int i = 0; i < 7; i++) {
        __syncthreads();                             // buffer (i+2)%3 now free
        if (i <= 4) {
            stageA(i + 2, (i + 2) % 3);
            asm volatile("cp.async.wait_group 2;");
        } else if (i == 5) {
            asm volatile("cp.async.wait_group 1;");
        } else {
            asm volatile("cp.async.wait_group 0;");
        }
        __syncthreads();

        const char* kB = sm + (i % 3) * ACHUNK;
        const char* vB = kB + TEN;

        // software pipeline over 7 columns (16B each = 2 pos-pairs)
        ulonglong2 kk[8], vv[4], kk2[8], vv2[4];
        auto loadCol = [&](int u, ulonglong2* k8, ulonglong2* v4) {
            const int col = wid + u * 8;
            #pragma unroll
            for (int i2 = 0; i2 < 8; i2++) {
                const int c1 = ti * 8 + i2;
                k8[i2] = *(const ulonglong2*)(kB + c1 * ROWB
                          + ((col ^ ((c1 >> 2) & 7)) << 4));
            }
            #pragma unroll
            for (int j = 0; j < 4; j++) {
                const int c2 = tj * 4 + j;
                v4[j] = *(const ulonglong2*)(vB + c2 * ROWB
                          + ((col ^ tj) << 4));
            }
        };

        loadCol(0, kk, vv);
        #pragma unroll
        for (int u = 0; u < 7; u++) {
            if (u < 6) loadCol(u + 1, kk2, vv2);
            #pragma unroll
            for (int i2 = 0; i2 < 8; i2++)
                #pragma unroll
                for (int j = 0; j < 4; j++) {
                    fma2(acc[i2][j], kk[i2].x, vv[j].x);
                    fma2(acc[i2][j], kk[i2].y, vv[j].y);
                }
            if (u < 6) {
                #pragma unroll
                for (int t = 0; t < 8; t++) kk[t] = kk2[t];
                #pragma unroll
                for (int t = 0; t < 4; t++) vv[t] = vv2[t];
            }
        }
        __syncthreads();
    }

    // ---------------- reduction: 8 warps -> psd (duplicated pairs) --------
    float* red = (float*)(sm + RED_OFF);
    #pragma unroll
    for (int i2 = 0; i2 < 8; i2++)
        #pragma unroll
        for (int j = 0; j < 4; j++)
            red[wid * 1024 + (ti * 8 + i2) * 32 + tj * 4 + j] =
                lo32(acc[i2][j]) + hi32(acc[i2][j]);
    __syncthreads();                                 // all A compute done

    // stage first two Q chunks (reuses A ring region; safe after sync)
    auto stageB = [&](int ch, int buf) {
        const unsigned bufb = sm32 + buf * BCH;
        const int gofs = base + ch * 448;
        #pragma unroll
        for (int it = 0; it < 7; it++) {
            int idx = it * 256 + tid;                // 0..1791
            int c = idx / 56;
            int g = idx - c * 56;
            int r = g / 7;
            int w4 = g - r * 7;
            cp16(bufb + c * ROWB + g * 16,
                 Q + gofs + c * SPATIAL + r * 56 + w4 * 4);
        }
        asm volatile("cp.async.commit_group;");
    };
    stageB(0, 0);
    stageB(1, 1);

    // build psd while B0/B1 stream in
    float* psd = (float*)(sm + PSD_OFF);             // [c1][c2 dup2] 2048 floats
    #pragma unroll
    for (int t = 0; t < 4; t++) {
        const int cell = tid + t * 256;
        const int c1 = cell >> 5, c2 = cell & 31;
        float s = red[cell];
        #pragma unroll
        for (int w = 1; w < 8; w++) s += red[w * 1024 + cell];
        s *= SCALE2;
        *(ull*)&psd[c1 * 64 + c2 * 2] = rep2(s);
    }

    // ---------------- Phase B: out = Q * P --------------------------------
    const int c2g  = tid & 7;            // 4 c2 each
    const int posg = tid >> 3;            // 0..31, active < 28
    const bool act = posg < 28;
    const int pbase = posg * 8;

    for (int ck = 0; ck < 7; ck++) {
        __syncthreads();
        if (ck <= 4) {
            stageB(ck + 2, (ck + 2) % 3);
            asm volatile("cp.async.wait_group 2;");
        } else if (ck == 5) {
            asm volatile("cp.async.wait_group 1;");
        } else {
            asm volatile("cp.async.wait_group 0;");
        }
        __syncthreads();

        if (act) {
            const char* qB = sm + (ck % 3) * BCH;

            ull a[4][4];
            #pragma unroll
            for (int p = 0; p < 4; p++)
                #pragma unroll
                for (int j = 0; j < 4; j++) a[p][j] = 0ull;

            #pragma unroll
            for (int c1 = 0; c1 < 32; c1++) {
                ulonglong2 qa = *(const ulonglong2*)(qB + c1 * ROWB + pbase * 4);
                ulonglong2 qb = *(const ulonglong2*)(qB + c1 * ROWB + pbase * 4 + 16);
                ulonglong2 pd0 = *(const ulonglong2*)&psd[c1 * 64 + c2g * 8];
                ulonglong2 pd1 = *(const ulonglong2*)&psd[c1 * 64 + c2g * 8 + 4];
                fma2(a[0][0], qa.x, pd0.x); fma2(a[1][0], qa.y, pd0.x);
                fma2(a[2][0], qb.x, pd0.x); fma2(a[3][0], qb.y, pd0.x);
                fma2(a[0][1], qa.x, pd0.y); fma2(a[1][1], qa.y, pd0.y);
                fma2(a[2][1], qb.x, pd0.y); fma2(a[3][1], qb.y, pd0.y);
                fma2(a[0][2], qa.x, pd1.x); fma2(a[1][2], qa.y, pd1.x);
                fma2(a[2][2], qb.x, pd1.x); fma2(a[3][2], qb.y, pd1.x);
                fma2(a[0][3], qa.x, pd1.y); fma2(a[1][3], qa.y, pd1.y);
                fma2(a[2][3], qb.x, pd1.y); fma2(a[3][3], qb.y, pd1.y);
            }

            const int obase = base + ck * 448;
            #pragma unroll
            for (int j = 0; j < 4; j++) {
                const int c2 = c2g * 4 + j;
                #pragma unroll
                for (int h = 0; h < 2; h++) {
                    const int p  = pbase + h * 4;
                    const int rr = p / 28;
                    const int ww = p - rr * 28;
                    float4 o4;
                    o4.x = lo32(a[2 * h][j]);
                    o4.y = hi32(a[2 * h][j]);
                    o4.z = lo32(a[2 * h + 1][j]);
                    o4.w = hi32(a[2 * h + 1][j]);
                    *(float4*)(O + obase + c2 * SPATIAL + rr * 56 + ww) = o4;
                }
            }
        }
    }
}

// ---------------------------------------------------------------------------
extern "C" void kernel_launch(void* const* d_in, const int* in_sizes, int n_in,
                              void* d_out, int out_size) {
    const float* q = (const float*)d_in[0];
    const float* k = (const float*)d_in[1];
    const float* v = (const float*)d_in[2];
    float* out = (float*)d_out;

    cudaFuncSetAttribute(fused, cudaFuncAttributeMaxDynamicSharedMemorySize, SMEM_TOT);
    fused<<<NBW, 256, SMEM_TOT>>>(k, v, q, out);
}